// round 9
// baseline (speedup 1.0000x reference)
#include <cuda_runtime.h>

#define N 128
#define BATCH 32
#define NITERS 500
#define RHO 0.1f
#define SIGMA 1e-6f
#define RELAX 1.6f
#define ALPHA 0.5f
#define DELTA 10.0f

typedef unsigned long long ull;

union F2U { ull u; float2 f; };
__device__ __forceinline__ ull pack2(float x, float y) { F2U u; u.f = make_float2(x, y); return u.u; }
__device__ __forceinline__ ull fma2(ull a, ull b, ull c) {
    ull d; asm("fma.rn.f32x2 %0, %1, %2, %3;" : "=l"(d) : "l"(a), "l"(b), "l"(c)); return d;
}
__device__ __forceinline__ ull add2(ull a, ull b) {
    ull d; asm("add.rn.f32x2 %0, %1, %2;" : "=l"(d) : "l"(a), "l"(b)); return d;
}
__device__ __forceinline__ ull mul2(ull a, ull b) {
    ull d; asm("mul.rn.f32x2 %0, %1, %2;" : "=l"(d) : "l"(a), "l"(b)); return d;
}

// dd buffers: rows 0-63 at p*64, rows 64-127 at 132+p*64 (bank skew 4)
#define DD_A(p) ((p) * 64)
#define DD_B(p) (132 + (p) * 64)

// Warp roles (352 threads):
//   warps 0-7 : matvec (row j = w*16+(l&15), half hf = l>>4; W half-row in regs,
//               persisting from the Gauss-Jordan inversion). Phase A only.
//   warps 8-9 : epilogue; thread i=(w-8)*32+l owns rows 2i,2i+1, all state f32x2-
//               packed across the row pair. Phase B only.
//   warp 10   : scalar equality row (phase A, pipelined one iteration ahead).
__global__ void __launch_bounds__(352, 1)
mvo_kernel(const float* __restrict__ X, const float* __restrict__ V,
           const float* __restrict__ beta, const float* __restrict__ thE,
           const float* __restrict__ thD, const float* __restrict__ lg1,
           const float* __restrict__ lg2, const float* __restrict__ bvec,
           const float* __restrict__ hvec, float* __restrict__ out) {
    __shared__ __align__(16) float sddpool[260];
    __shared__ __align__(16) float sth[272];        // th[hf] at hf*144 + j
    __shared__ __align__(16) ull rowbuf[2][64];     // pivot export; later syp staging
    __shared__ __align__(16) float sq[N];
    __shared__ float red8[8];
    __shared__ float sQ1;
    __shared__ float c2buf[2];
    __shared__ __align__(16) float sx[N];

    const int tid = threadIdx.x;
    const int b = blockIdx.x;
    const int w = tid >> 5, l = tid & 31;
    const bool rowt = (tid < 256);
    const bool epit = (w == 8 || w == 9);
    const int j = (w & 7) * 16 + (l & 15);
    const int hf = l >> 4;
    const int ei = (w - 8) * 32 + l;                // epi thread index 0..63

    if (tid < 128) sx[tid] = X[b * N + tid];
    if (tid == 0) { c2buf[0] = 0.f; c2buf[1] = 0.f; }
    __syncthreads();

    // ---------- per-row constants + y_pred (matvec warps) ----------
    float ypv = 0.f;
    ull rr[32];
    if (rowt) {
        float acc = 0.f;
        {
            const float* xp = sx + hf * 64;
            const float* bp = beta + (hf * 64) * N + j;
#pragma unroll 8
            for (int k = 0; k < 64; k++) acc = fmaf(xp[k], bp[k * N], acc);
        }
        ypv = acc + __shfl_xor_sync(0xffffffffu, acc, 16);
        if (hf == 0) out[BATCH * N + b * N + j] = ypv;

        const float g2 = exp10f(lg2[0]);
        const float sg = 1.0f / (1.0f + expf(-thD[j]));
        const float dg = 2.0f * (1.0f - ALPHA) * g2 * sg * sg + 3.0f * RHO + SIGMA;
        const float2* vrow = (const float2*)(V + j * N + hf * 64);
#pragma unroll
        for (int m = 0; m < 32; m++) {
            float2 v = vrow[m];
            float a = fmaf(2.0f * DELTA, v.x, 2.0f * RHO);
            float c = fmaf(2.0f * DELTA, v.y, 2.0f * RHO);
            int gc = hf * 64 + 2 * m;
            if (gc == j)     a += dg;
            if (gc + 1 == j) c += dg;
            rr[m] = pack2(a, c);
        }
    }

    // ---------- 128 Gauss-Jordan pivots (1 barrier each) ----------
#pragma unroll
    for (int k = 0; k < N; k++) {
        ull* buf = rowbuf[k & 1];
        if (rowt && j == k) {
            ulonglong2* buf2 = (ulonglong2*)buf;
#pragma unroll
            for (int m = 0; m < 16; m++)
                buf2[hf * 16 + m] = make_ulonglong2(rr[2 * m], rr[2 * m + 1]);
        }
        __syncthreads();
        if (rowt) {
            const float* bf = (const float*)buf;
            const float d = 1.0f / bf[k];
            const int mm = (k & 63) >> 1;
            F2U u; u.u = rr[mm];
            float fown = (k & 1) ? u.f.y : u.f.x;
            float f = __shfl_sync(0xffffffffu, fown, (l & 15) | ((k >> 6) << 4));
            const ulonglong2* bh = (const ulonglong2*)(buf + hf * 32);
            if (j == k) {
                ull d2 = pack2(d, d);
#pragma unroll
                for (int m = 0; m < 32; m++) rr[m] = mul2(rr[m], d2);
                if (hf == (k >> 6)) {
                    F2U t; t.u = rr[mm];
                    if (k & 1) t.f.y = d; else t.f.x = d;
                    rr[mm] = t.u;
                }
            } else {
                float fd = f * d;
                ull nf2 = pack2(-fd, -fd);
#pragma unroll
                for (int m = 0; m < 16; m++) {
                    ulonglong2 bb = bh[m];
                    rr[2 * m]     = fma2(nf2, bb.x, rr[2 * m]);
                    rr[2 * m + 1] = fma2(nf2, bb.y, rr[2 * m + 1]);
                }
                if (hf == (k >> 6)) {
                    F2U t; t.u = rr[mm];
                    if (k & 1) t.f.y = -fd; else t.f.x = -fd;
                    rr[mm] = t.u;
                }
            }
        }
    }

    // ---------- q = W@1, Q1; stage y_pred for epi warps ----------
    float* syp = (float*)rowbuf;    // rowbuf is free now
    if (rowt) {
        ull s0 = 0, s1 = 0, s2 = 0, s3 = 0;
#pragma unroll
        for (int m = 0; m < 32; m += 4) {
            s0 = add2(s0, rr[m]);     s1 = add2(s1, rr[m + 1]);
            s2 = add2(s2, rr[m + 2]); s3 = add2(s3, rr[m + 3]);
        }
        F2U ts; ts.u = add2(add2(s0, s1), add2(s2, s3));
        float qh = ts.f.x + ts.f.y;
        float qs = qh + __shfl_xor_sync(0xffffffffu, qh, 16);
        if (hf == 0) { sq[j] = qs; syp[j] = ypv; }
        float r = qs;
        r += __shfl_xor_sync(0xffffffffu, r, 8);
        r += __shfl_xor_sync(0xffffffffu, r, 4);
        r += __shfl_xor_sync(0xffffffffu, r, 2);
        r += __shfl_xor_sync(0xffffffffu, r, 1);
        if (l == 0) red8[w] = r;
    }
    __syncthreads();
    if (tid == 0) {
        float t = 0.f;
#pragma unroll
        for (int i = 0; i < 8; i++) t += red8[i];
        sQ1 = t;
    }
    __syncthreads();

    const float omr = 1.0f - RELAX;

    // ---------- epi-warp constants + initial dd ----------
    ull yp2_2 = 0, mpt2_2 = 0, qj2 = 0;
    float up1x = 0.f, up1y = 0.f;
    ull s2s = 0, hsu2 = 0;
    ull Xp1 = 0, Xp2 = 0, A2 = 0, A3 = 0, a1r2 = 0;
    const ull ABS2 = 0x7fffffff7fffffffull;
    const ull SGN2 = 0x8000000080000000ull;
    if (epit) {
        float2 yv = *(float2*)&syp[2 * ei];
        yp2_2 = pack2(2.0f * yv.x, 2.0f * yv.y);
        const float g1v = exp10f(lg1[0]);
        float2 te = *(const float2*)&thE[2 * ei];
        float e0 = 1.0f / (1.0f + expf(-te.x));
        float e1 = 1.0f / (1.0f + expf(-te.y));
        mpt2_2 = pack2(-2.0f * ALPHA * g1v * e0, -2.0f * ALPHA * g1v * e1);
        float2 hv = *(const float2*)&hvec[2 * ei];
        up1x = hv.x; up1y = hv.y;
        qj2 = *(ull*)&sq[2 * ei];
        s2s = mpt2_2;
        const float hirs = 0.5f / (RHO + SIGMA);
        hsu2 = mul2(s2s, pack2(hirs, hirs));
        // initial dd = yp2
        float* dst = (w == 8) ? &sddpool[DD_A(0) + 2 * l] : &sddpool[DD_B(0) + 2 * l];
        *(float2*)dst = make_float2(2.0f * yv.x, 2.0f * yv.y);
    }

    // scalar warp constants
    float4 qa = make_float4(0, 0, 0, 0), qb = qa;
    float Q1v = 0.f, b0 = 0.f;
    if (w == 10 && l < 16) {
        qa = ((const float4*)sq)[l];
        qb = ((const float4*)sq)[16 + l];
        Q1v = sQ1;
        b0 = bvec[0];
    }
    float c2loc = 0.f, Y0 = 0.f, z0 = 0.f;
    float c2s = 0.f;
    __syncthreads();

    const ull R2v  = pack2(RELAX, RELAX);
    const ull mR2  = pack2(-RELAX, -RELAX);
    const ull OMR2 = pack2(omr, omr);
    const ull H2p  = pack2(0.5f, 0.5f);
    const ull H2m  = pack2(-0.5f, -0.5f);
    const ull TWO2 = pack2(2.0f, 2.0f);
    const ull RHO2 = pack2(RHO, RHO);
    const ull mRHO2 = pack2(-RHO, -RHO);
    const ull m2RHO2 = pack2(-2.0f * RHO, -2.0f * RHO);
    const ull HIRS2 = pack2(0.5f / (RHO + SIGMA), 0.5f / (RHO + SIGMA));
    const float qjloc = (rowt ? 0.f : 0.f);
    (void)qjloc;

    // ---------- 500-iteration ADMM (2 phases, 2 barriers) ----------
#pragma unroll 2
    for (int it = 0; it < NITERS; it++) {
        const int p = it & 1;
        // ---- phase A ----
        if (rowt) {
            const ulonglong2* dds =
                (const ulonglong2*)(sddpool + (hf ? DD_B(p) : DD_A(p)));
            ull a0 = 0ull, a1 = 0ull, a2 = 0ull, a3 = 0ull;
#pragma unroll
            for (int m = 0; m < 8; m++) {
                ulonglong2 d0 = dds[2 * m];
                ulonglong2 d1 = dds[2 * m + 1];
                a0 = fma2(rr[4 * m + 0], d0.x, a0);
                a1 = fma2(rr[4 * m + 1], d0.y, a1);
                a2 = fma2(rr[4 * m + 2], d1.x, a2);
                a3 = fma2(rr[4 * m + 3], d1.y, a3);
            }
            F2U acc; acc.u = add2(add2(a0, a1), add2(a2, a3));
            sth[hf * 144 + j] = acc.f.x + acc.f.y;
        } else if (w == 10) {
            if (l < 16) {
                const float4* dA = (const float4*)(sddpool + DD_A(p));
                const float4* dB = (const float4*)(sddpool + DD_B(p));
                float4 da = dA[l], db = dB[l];
                float r = qa.x * da.x + qa.y * da.y + qa.z * da.z + qa.w * da.w
                        + qb.x * db.x + qb.y * db.y + qb.z * db.z + qb.w * db.w;
                r += __shfl_xor_sync(0xffffu, r, 8);
                r += __shfl_xor_sync(0xffffu, r, 4);
                r += __shfl_xor_sync(0xffffu, r, 2);
                r += __shfl_xor_sync(0xffffu, r, 1);
                float zt0 = fmaf(c2loc, Q1v, r);
                float zr0 = fmaf(omr, z0, RELAX * zt0);
                Y0 = Y0 + zr0 - b0;
                z0 = b0;
                c2loc = 2.0f * RHO * (b0 - Y0);
                if (l == 0) c2buf[p ^ 1] = c2loc;
            }
        } else {
            c2s = c2buf[p];     // epi prefetch (written at iter-1 phase A)
        }
        __syncthreads();
        // ---- phase B (epilogue warps) ----
        if (epit) {
            F2U tha, thb;
            tha.f = *(float2*)&sth[2 * ei];
            thb.f = *(float2*)&sth[144 + 2 * ei];
            ull TH = add2(tha.u, thb.u);
            ull t2 = fma2(pack2(c2s, c2s), qj2, TH);
            ull XT1 = fma2(H2p, t2, hsu2);
            ull XT2 = fma2(H2m, t2, hsu2);
            ull V2 = fma2(mR2, XT1, A2);
            ull V3 = fma2(mR2, XT2, A3);
            ull av2 = V2 & ABS2;
            ull av3 = V3 & ABS2;
            ull v1 = fma2(mR2, t2, a1r2);
            F2U vz; vz.u = v1;
            F2U z1; z1.f.x = fminf(vz.f.x, up1x); z1.f.y = fminf(vz.f.y, up1y);
            ull u1 = fma2(TWO2, z1.u, v1 ^ SGN2);
            ull ddl = fma2(m2RHO2, u1, yp2_2);
            ddl = fma2(RHO2, av2, ddl);
            ddl = fma2(mRHO2, av3, ddl);
            F2U dv; dv.u = ddl;
            float* dst = (w == 8) ? &sddpool[DD_A(p ^ 1) + 2 * l]
                                  : &sddpool[DD_B(p ^ 1) + 2 * l];
            *(float2*)dst = dv.f;
            // trailing (off next critical path)
            s2s = fma2(RHO2, av2, fma2(RHO2, av3, mpt2_2));
            hsu2 = mul2(s2s, HIRS2);
            a1r2 = fma2(mR2, z1.u, v1);
            {
                ull o2 = mul2(OMR2, V2);
                F2U a, o; a.u = V2; o.u = o2;
                F2U m; m.f.x = fmaxf(a.f.x, o.f.x); m.f.y = fmaxf(a.f.y, o.f.y);
                A2 = m.u;
            }
            {
                ull o3 = mul2(OMR2, V3);
                F2U a, o; a.u = V3; o.u = o3;
                F2U m; m.f.x = fmaxf(a.f.x, o.f.x); m.f.y = fmaxf(a.f.y, o.f.y);
                A3 = m.u;
            }
            Xp1 = fma2(R2v, XT1, mul2(OMR2, Xp1));
            Xp2 = fma2(R2v, XT2, mul2(OMR2, Xp2));
        }
        __syncthreads();
    }

    if (epit) {
        F2U x1u, x2u; x1u.u = Xp1; x2u.u = Xp2;
        *(float2*)&out[b * N + 2 * ei] =
            make_float2(x1u.f.x - x2u.f.x, x1u.f.y - x2u.f.y);
    }
}

// ---------------- launcher ----------------
extern "C" void kernel_launch(void* const* d_in, const int* in_sizes, int n_in,
                              void* d_out, int out_size) {
    const float* X    = (const float*)d_in[0];
    const float* V    = (const float*)d_in[1];
    const float* beta = (const float*)d_in[2];
    const float* thE  = (const float*)d_in[3];
    const float* thD  = (const float*)d_in[4];
    const float* lg1  = (const float*)d_in[5];
    const float* lg2  = (const float*)d_in[6];
    const float* bvec = (const float*)d_in[8];
    const float* hvec = (const float*)d_in[10];
    float* out = (float*)d_out;

    mvo_kernel<<<BATCH, 352>>>(X, V, beta, thE, thD, lg1, lg2, bvec, hvec, out);
}